// round 6
// baseline (speedup 1.0000x reference)
#include <cuda_runtime.h>
#include <cuda_bf16.h>
#include <math.h>

#define MAX_T 11
#define HIDDEN 768
#define MAX_S 64
#define MAX_ROWS 64

// Scratch (no device allocation allowed). All counters return to initial
// state at the end of every launch -> deterministic across graph replays.
__device__ float        g_exp[MAX_S * MAX_T];
__device__ float        g_w[MAX_ROWS];
__device__ int          g_count  = 0;   // dot-block completion counter
__device__ int          g_count2 = 0;   // whole-grid completion counter
__device__ volatile int g_flag   = 0;   // weights-ready flag

__global__ void __launch_bounds__(256)
fused(const float4* __restrict__ bert,
      const float*  __restrict__ hist,
      const float4* __restrict__ mtl,
      const float*  __restrict__ W,
      const float*  __restrict__ b,
      const int*    __restrict__ slice_mask,
      float4* __restrict__ out_bert,
      float4* __restrict__ out_mtl,
      float*  __restrict__ out_probs,
      int rows, int S, int vec_bert, int vec_mtl,
      int dot_blocks, int bert_blocks, int total_blocks)
{
    int tid = threadIdx.x;

    if (blockIdx.x < (unsigned)dot_blocks) {
        // ================= Phase A: one (s,t) dot product per block ========
        __shared__ int   s_mask[MAX_S];
        __shared__ int   s_offs[MAX_S + 1];
        __shared__ float s_red[6];
        __shared__ int   s_isLast;
        __shared__ float s_probs[MAX_S * MAX_T];

        int i = blockIdx.x;
        int s = i / MAX_T, t = i - s * MAX_T;

        if (tid < S) s_mask[tid] = slice_mask[tid];
        __syncthreads();
        if (tid == 0) {
            int acc = 0;
            for (int k = 0; k < S; k++) { s_offs[k] = acc; acc += s_mask[k]; }
            s_offs[S] = acc;
        }
        __syncthreads();

        int ns  = s_mask[s];
        int pad = MAX_T - ns;

        if (t < pad) {
            if (tid == 0) g_exp[i] = 0.f;
        } else if (tid < HIDDEN / 4) {
            int idx = s_offs[s] + t - pad;
            if (idx < 0) idx = 0;
            if (idx >= rows) idx = rows - 1;
            const float4* h4 = (const float4*)(hist + (size_t)idx * HIDDEN);
            const float4* w4 = (const float4*)W;
            float4 hv = h4[tid];
            float4 wv = w4[tid];
            float v = hv.x * wv.x + hv.y * wv.y + hv.z * wv.z + hv.w * wv.w;
            #pragma unroll
            for (int o = 16; o; o >>= 1) v += __shfl_xor_sync(0xffffffffu, v, o);
            if ((tid & 31) == 0) s_red[tid >> 5] = v;
        }
        __syncthreads();
        if (t >= pad && tid == 0) {
            float tot = s_red[0] + s_red[1] + s_red[2] +
                        s_red[3] + s_red[4] + s_red[5];
            g_exp[i] = __expf(tot + b[0]);
        }
        __threadfence();
        __syncthreads();
        if (tid == 0)
            s_isLast = (atomicAdd(&g_count, 1) == dot_blocks - 1) ? 1 : 0;
        __syncthreads();

        if (s_isLast) {
            // ---------- finalize: softmax + per-row weights ----------
            if (tid < S) {
                float e[MAX_T];
                float sum = 0.f;
                #pragma unroll
                for (int tt = 0; tt < MAX_T; tt++) {
                    e[tt] = g_exp[tid * MAX_T + tt];
                    sum += e[tt];
                }
                float inv = 1.f / sum;
                #pragma unroll
                for (int tt = 0; tt < MAX_T; tt++) {
                    float p = e[tt] * inv;
                    s_probs[tid * MAX_T + tt] = p;
                    out_probs[tid * MAX_T + tt] = p;
                }
            }
            __syncthreads();
            if (tid < rows) {
                int seg = S - 1;
                for (int k = 0; k < S; k++)
                    if (tid < s_offs[k + 1]) { seg = k; break; }
                int pos = tid - s_offs[seg];
                int tt = (MAX_T - s_mask[seg]) + pos;
                if (tt < 0) tt = 0;
                if (tt > MAX_T - 1) tt = MAX_T - 1;
                g_w[tid] = s_probs[seg * MAX_T + tt];
            }
            __threadfence();
            __syncthreads();
            if (tid == 0) {
                g_count = 0;          // reset for next replay
                g_flag  = 1;          // publish weights
            }
        }
    } else {
        // ================= Phase B: weighted segment sum ===================
        __shared__ int sh_off, sh_n;

        int wid = blockIdx.x - dot_blocks;
        int per_s = bert_blocks + 1;
        int s = wid / per_s;
        int x = wid - s * per_s;

        if (tid == 0) {
            int acc = 0;
            for (int k = 0; k < s; k++) acc += slice_mask[k];
            sh_off = acc;
            sh_n   = slice_mask[s];
        }
        __syncthreads();
        int off = sh_off, n = sh_n;

        const float4* in;
        float4* out;
        int vec, j;
        if (x < bert_blocks) {
            in = bert; out = out_bert; vec = vec_bert;
            j = x * blockDim.x + tid;
        } else {
            in = mtl; out = out_mtl; vec = vec_mtl;
            j = tid;
        }
        bool active = (j < vec);

        // Preload up to 4 rows into registers BEFORE weights are ready:
        // overlaps the entire DRAM traffic with the dot/finalize phase.
        float4 v[4];
        int npre = n < 4 ? n : 4;
        if (active) {
            #pragma unroll
            for (int k = 0; k < 4; k++)
                if (k < npre) v[k] = in[(size_t)(off + k) * vec + j];
        }

        // Wait for weights.
        if (g_flag == 0) {
            while (g_flag == 0) __nanosleep(64);
        }
        __threadfence();

        if (active) {
            float4 acc = make_float4(0.f, 0.f, 0.f, 0.f);
            #pragma unroll
            for (int k = 0; k < 4; k++) {
                if (k < npre) {
                    float w = g_w[off + k];
                    acc.x += w * v[k].x; acc.y += w * v[k].y;
                    acc.z += w * v[k].z; acc.w += w * v[k].w;
                }
            }
            for (int k = 4; k < n; k++) {        // rare tail (n>4)
                float w = g_w[off + k];
                float4 u = in[(size_t)(off + k) * vec + j];
                acc.x += w * u.x; acc.y += w * u.y;
                acc.z += w * u.z; acc.w += w * u.w;
            }
            out[(size_t)s * vec + j] = acc;
        }
    }

    // ============== Tail: last block of grid resets the flag ==============
    __syncthreads();
    if (tid == 0) {
        if (atomicAdd(&g_count2, 1) == total_blocks - 1) {
            g_flag   = 0;
            g_count2 = 0;
        }
    }
}

extern "C" void kernel_launch(void* const* d_in, const int* in_sizes, int n_in,
                              void* d_out, int out_size)
{
    const float* bert       = (const float*)d_in[0];
    const float* hist       = (const float*)d_in[1];
    const float* mtl        = (const float*)d_in[2];
    const float* W          = (const float*)d_in[3];
    const float* b          = (const float*)d_in[4];
    const int*   slice_mask = (const int*)  d_in[5];

    int rows = in_sizes[1] / HIDDEN;                 // 64
    int seqh = in_sizes[0] / rows;                   // 512*768
    int per_s = seqh + HIDDEN + MAX_T;
    int S = out_size / per_s;                        // 16

    float* out        = (float*)d_out;
    float* out_bert   = out;
    float* out_mtl    = out_bert + (size_t)S * seqh;
    float* out_probs  = out_mtl  + (size_t)S * HIDDEN;

    int vec_bert = seqh / 4;                         // 98304
    int vec_mtl  = HIDDEN / 4;                       // 192
    int bert_blocks = (vec_bert + 255) / 256;        // 384
    int dot_blocks  = S * MAX_T;                     // 176
    int total_blocks = dot_blocks + S * (bert_blocks + 1);

    fused<<<total_blocks, 256>>>((const float4*)bert, hist, (const float4*)mtl,
                                 W, b, slice_mask,
                                 (float4*)out_bert, (float4*)out_mtl, out_probs,
                                 rows, S, vec_bert, vec_mtl,
                                 dot_blocks, bert_blocks, total_blocks);
}

// round 7
// speedup vs baseline: 1.4742x; 1.4742x over previous
#include <cuda_runtime.h>
#include <cuda_bf16.h>
#include <math.h>

#define MAX_T 11
#define HIDDEN 768
#define MAX_S 64

// Fully independent blocks: each block recomputes its slice's <=MAX_T weights
// from hist/W (L2-resident, ~12KB) -- no inter-block sync of any kind.
__global__ void __launch_bounds__(256)
fused(const float4* __restrict__ bert,
      const float*  __restrict__ hist,
      const float4* __restrict__ mtl,
      const float*  __restrict__ W,
      const float*  __restrict__ b,
      const int*    __restrict__ slice_mask,
      float4* __restrict__ out_bert,
      float4* __restrict__ out_mtl,
      float*  __restrict__ out_probs,
      int rows, int S, int vec_bert, int vec_mtl, int bert_blocks)
{
    __shared__ int   s_mask[MAX_S];
    __shared__ float s_e[MAX_T];

    int tid = threadIdx.x;
    int s = blockIdx.y;
    int x = blockIdx.x;

    if (tid < S) s_mask[tid] = slice_mask[tid];
    __syncthreads();

    // Per-thread prefix sum over <=15 smem ints (cheap, no sync needed).
    int off = 0;
    #pragma unroll 4
    for (int k = 0; k < s; k++) off += s_mask[k];
    int n = s_mask[s];
    if (n > MAX_T) n = MAX_T;

    // ---- Issue the big DRAM preloads FIRST (bandwidth-bound part) ----
    const float4* in;
    float4* outp;
    int vec, j;
    if (x < bert_blocks) {
        in = bert; outp = out_bert; vec = vec_bert;
        j = x * blockDim.x + tid;
    } else {
        in = mtl; outp = out_mtl; vec = vec_mtl;
        j = tid;
    }
    bool active = (j < vec);

    float4 v[4];
    int npre = n < 4 ? n : 4;
    if (active) {
        #pragma unroll
        for (int k = 0; k < 4; k++)
            if (k < npre) v[k] = in[(size_t)(off + k) * vec + j];
    }

    // ---- Redundant per-block weight computation (L2-hot after wave 1) ----
    // warp d computes dot(hist[off+d], W) for d, d+8, ...
    int warp = tid >> 5, lane = tid & 31;
    for (int d = warp; d < n; d += 8) {
        int idx = off + d;
        if (idx < 0) idx = 0;
        if (idx >= rows) idx = rows - 1;
        const float4* h4 = (const float4*)(hist + (size_t)idx * HIDDEN);
        const float4* w4 = (const float4*)W;
        float acc = 0.f;
        #pragma unroll
        for (int c = lane; c < HIDDEN / 4; c += 32) {
            float4 hv = h4[c];
            float4 wv = w4[c];
            acc += hv.x * wv.x + hv.y * wv.y + hv.z * wv.z + hv.w * wv.w;
        }
        #pragma unroll
        for (int o = 16; o; o >>= 1) acc += __shfl_xor_sync(0xffffffffu, acc, o);
        if (lane == 0) s_e[d] = __expf(acc + b[0]);
    }
    __syncthreads();

    float sum = 0.f;
    #pragma unroll 4
    for (int k = 0; k < n; k++) sum += s_e[k];
    float inv = 1.f / sum;

    // ---- Weighted segment sum with preloaded registers ----
    if (active) {
        float4 acc = make_float4(0.f, 0.f, 0.f, 0.f);
        #pragma unroll
        for (int k = 0; k < 4; k++) {
            if (k < npre) {
                float w = s_e[k] * inv;
                acc.x += w * v[k].x; acc.y += w * v[k].y;
                acc.z += w * v[k].z; acc.w += w * v[k].w;
            }
        }
        for (int k = 4; k < n; k++) {          // tail only if n > 4
            float w = s_e[k] * inv;
            float4 u = in[(size_t)(off + k) * vec + j];
            acc.x += w * u.x; acc.y += w * u.y;
            acc.z += w * u.z; acc.w += w * u.w;
        }
        outp[(size_t)s * vec + j] = acc;
    }

    // ---- The mtl block of each slice also writes probs (16x11 floats) ----
    if (x == bert_blocks && tid < MAX_T) {
        int pad = MAX_T - n;
        out_probs[s * MAX_T + tid] =
            (tid < pad) ? 0.f : s_e[tid - pad] * inv;
    }
}

extern "C" void kernel_launch(void* const* d_in, const int* in_sizes, int n_in,
                              void* d_out, int out_size)
{
    const float* bert       = (const float*)d_in[0];
    const float* hist       = (const float*)d_in[1];
    const float* mtl        = (const float*)d_in[2];
    const float* W          = (const float*)d_in[3];
    const float* b          = (const float*)d_in[4];
    const int*   slice_mask = (const int*)  d_in[5];

    int rows = in_sizes[1] / HIDDEN;                 // 64
    int seqh = in_sizes[0] / rows;                   // 512*768
    int per_s = seqh + HIDDEN + MAX_T;
    int S = out_size / per_s;                        // 16

    float* out        = (float*)d_out;
    float* out_bert   = out;
    float* out_mtl    = out_bert + (size_t)S * seqh;
    float* out_probs  = out_mtl  + (size_t)S * HIDDEN;

    int vec_bert = seqh / 4;                         // 98304
    int vec_mtl  = HIDDEN / 4;                       // 192
    int bert_blocks = (vec_bert + 255) / 256;        // 384

    dim3 g(bert_blocks + 1, S);                      // (385, 16)
    fused<<<g, 256>>>((const float4*)bert, hist, (const float4*)mtl,
                      W, b, slice_mask,
                      (float4*)out_bert, (float4*)out_mtl, out_probs,
                      rows, S, vec_bert, vec_mtl, bert_blocks);
}

// round 8
// speedup vs baseline: 2.1355x; 1.4486x over previous
#include <cuda_runtime.h>
#include <cuda_bf16.h>
#include <math.h>

#define MAX_T 11
#define HIDDEN 768
#define MAX_S 64
#define MAX_ROWS 64

// Scratch (no device allocation allowed). Counters self-reset each launch.
__device__ float g_exp[MAX_S * MAX_T];
__device__ float g_w[MAX_ROWS];
__device__ int   g_count = 0;

// ---------------------------------------------------------------------------
// K1: weights producer. One block per (s,t); last block finalizes softmax +
// per-row weights. Triggers PDL completion immediately so K2 can start
// issuing its DRAM preloads underneath.
// ---------------------------------------------------------------------------
__global__ void __launch_bounds__(192)
k_weights(const float* __restrict__ hist,
          const float* __restrict__ W,
          const float* __restrict__ b,
          const int*   __restrict__ slice_mask,
          float* __restrict__ out_probs,
          int rows, int S, int dot_blocks)
{
    cudaTriggerProgrammaticLaunchCompletion();

    __shared__ int   s_mask[MAX_S];
    __shared__ int   s_offs[MAX_S + 1];
    __shared__ float s_red[6];
    __shared__ int   s_isLast;
    __shared__ float s_probs[MAX_S * MAX_T];

    int tid = threadIdx.x;
    int i = blockIdx.x;
    int s = i / MAX_T, t = i - s * MAX_T;

    if (tid < S) s_mask[tid] = slice_mask[tid];
    __syncthreads();
    if (tid == 0) {
        int acc = 0;
        for (int k = 0; k < S; k++) { s_offs[k] = acc; acc += s_mask[k]; }
        s_offs[S] = acc;
    }
    __syncthreads();

    int ns  = s_mask[s];
    int pad = MAX_T - ns;

    if (t < pad) {
        if (tid == 0) g_exp[i] = 0.f;
    } else if (tid < HIDDEN / 4) {
        int idx = s_offs[s] + t - pad;
        if (idx < 0) idx = 0;
        if (idx >= rows) idx = rows - 1;
        const float4* h4 = (const float4*)(hist + (size_t)idx * HIDDEN);
        const float4* w4 = (const float4*)W;
        float4 hv = h4[tid];
        float4 wv = w4[tid];
        float v = hv.x * wv.x + hv.y * wv.y + hv.z * wv.z + hv.w * wv.w;
        #pragma unroll
        for (int o = 16; o; o >>= 1) v += __shfl_xor_sync(0xffffffffu, v, o);
        if ((tid & 31) == 0) s_red[tid >> 5] = v;
    }
    __syncthreads();
    if (t >= pad && tid == 0) {
        float tot = s_red[0] + s_red[1] + s_red[2] +
                    s_red[3] + s_red[4] + s_red[5];
        g_exp[i] = __expf(tot + b[0]);
    }
    __threadfence();
    __syncthreads();
    if (tid == 0)
        s_isLast = (atomicAdd(&g_count, 1) == dot_blocks - 1) ? 1 : 0;
    __syncthreads();

    if (!s_isLast) return;

    // ---------- finalize (runs in exactly one block) ----------
    if (tid < S) {
        float e[MAX_T];
        float sum = 0.f;
        #pragma unroll
        for (int tt = 0; tt < MAX_T; tt++) {
            e[tt] = g_exp[tid * MAX_T + tt];
            sum += e[tt];
        }
        float inv = 1.f / sum;
        #pragma unroll
        for (int tt = 0; tt < MAX_T; tt++) {
            float p = e[tt] * inv;
            s_probs[tid * MAX_T + tt] = p;
            out_probs[tid * MAX_T + tt] = p;
        }
    }
    __syncthreads();
    if (tid < rows) {
        int seg = S - 1;
        for (int k = 0; k < S; k++)
            if (tid < s_offs[k + 1]) { seg = k; break; }
        int pos = tid - s_offs[seg];
        int tt = (MAX_T - s_mask[seg]) + pos;
        if (tt < 0) tt = 0;
        if (tt > MAX_T - 1) tt = MAX_T - 1;
        g_w[tid] = s_probs[seg * MAX_T + tt];
    }
    if (tid == 0) g_count = 0;   // reset for next graph replay
}

// ---------------------------------------------------------------------------
// K2: weighted segment sum (PDL secondary). Computes offsets from slice_mask
// (an input -> no dependency), issues all DRAM preloads, THEN waits for K1
// via the HW grid-dependency sync, then applies weights.
// ---------------------------------------------------------------------------
__global__ void __launch_bounds__(256)
k_segsum(const float4* __restrict__ bert,
         float4* __restrict__ out_bert,
         const float4* __restrict__ mtl,
         float4* __restrict__ out_mtl,
         const int* __restrict__ slice_mask,
         int vec_bert, int vec_mtl, int bert_blocks)
{
    __shared__ int sh_off, sh_n;

    int tid = threadIdx.x;
    int s = blockIdx.y;
    int x = blockIdx.x;

    if (tid == 0) {
        int acc = 0;
        for (int k = 0; k < s; k++) acc += slice_mask[k];
        sh_off = acc;
        sh_n   = slice_mask[s];
    }
    __syncthreads();
    int off = sh_off, n = sh_n;

    const float4* in;
    float4* out;
    int vec, j;
    if (x < bert_blocks) {
        in = bert; out = out_bert; vec = vec_bert;
        j = x * blockDim.x + tid;
    } else {
        in = mtl; out = out_mtl; vec = vec_mtl;
        j = tid;
    }
    bool active = (j < vec);

    // Preload up to 4 rows before the dependency sync: the full DRAM stream
    // overlaps K1's execution.
    float4 v[4];
    int npre = n < 4 ? n : 4;
    if (active) {
        #pragma unroll
        for (int k = 0; k < 4; k++)
            if (k < npre) v[k] = in[(size_t)(off + k) * vec + j];
    }

    cudaGridDependencySynchronize();   // HW wait for K1 grid completion

    if (active) {
        float4 acc = make_float4(0.f, 0.f, 0.f, 0.f);
        #pragma unroll
        for (int k = 0; k < 4; k++) {
            if (k < npre) {
                float w = g_w[off + k];
                acc.x += w * v[k].x; acc.y += w * v[k].y;
                acc.z += w * v[k].z; acc.w += w * v[k].w;
            }
        }
        for (int k = 4; k < n; k++) {          // tail only if n > 4
            float w = g_w[off + k];
            float4 u = in[(size_t)(off + k) * vec + j];
            acc.x += w * u.x; acc.y += w * u.y;
            acc.z += w * u.z; acc.w += w * u.w;
        }
        out[(size_t)s * vec + j] = acc;
    }
}

extern "C" void kernel_launch(void* const* d_in, const int* in_sizes, int n_in,
                              void* d_out, int out_size)
{
    const float* bert       = (const float*)d_in[0];
    const float* hist       = (const float*)d_in[1];
    const float* mtl        = (const float*)d_in[2];
    const float* W          = (const float*)d_in[3];
    const float* b          = (const float*)d_in[4];
    const int*   slice_mask = (const int*)  d_in[5];

    int rows = in_sizes[1] / HIDDEN;                 // 64
    int seqh = in_sizes[0] / rows;                   // 512*768
    int per_s = seqh + HIDDEN + MAX_T;
    int S = out_size / per_s;                        // 16

    float* out        = (float*)d_out;
    float* out_bert   = out;
    float* out_mtl    = out_bert + (size_t)S * seqh;
    float* out_probs  = out_mtl  + (size_t)S * HIDDEN;

    int vec_bert = seqh / 4;                         // 98304
    int vec_mtl  = HIDDEN / 4;                       // 192
    int bert_blocks = (vec_bert + 255) / 256;        // 384
    int dot_blocks  = S * MAX_T;                     // 176

    // Primary
    k_weights<<<dot_blocks, 192>>>(hist, W, b, slice_mask, out_probs,
                                   rows, S, dot_blocks);

    // Secondary with programmatic dependent launch
    cudaLaunchConfig_t cfg = {};
    cfg.gridDim  = dim3(bert_blocks + 1, S);
    cfg.blockDim = dim3(256);
    cudaLaunchAttribute attr[1];
    attr[0].id = cudaLaunchAttributeProgrammaticStreamSerialization;
    attr[0].val.programmaticStreamSerializationAllowed = 1;
    cfg.attrs = attr;
    cfg.numAttrs = 1;

    cudaLaunchKernelEx(&cfg, k_segsum,
                       (const float4*)bert, (float4*)out_bert,
                       (const float4*)mtl, (float4*)out_mtl,
                       slice_mask, vec_bert, vec_mtl, bert_blocks);
}